// round 14
// baseline (speedup 1.0000x reference)
#include <cuda_runtime.h>
#include <math.h>

#define BSZ   2
#define NN    512
#define DIN   256
#define HEADS 8
#define DOUT  64
#define HD    512
#define ROWS  1024
#define ALPHA 0.2f

// ---------------- packed fp32x2 helpers (Blackwell FADD2/FFMA2) ----------------
struct __align__(8) F2 { float x, y; };

__device__ __forceinline__ F2 f2add(F2 a, F2 b) {
    F2 r;
    asm("add.rn.f32x2 %0, %1, %2;"
        : "=l"(*reinterpret_cast<unsigned long long*>(&r))
        : "l"(*reinterpret_cast<unsigned long long*>(&a)),
          "l"(*reinterpret_cast<unsigned long long*>(&b)));
    return r;
}
__device__ __forceinline__ F2 f2fma(F2 a, F2 b, F2 c) {
    F2 r;
    asm("fma.rn.f32x2 %0, %1, %2, %3;"
        : "=l"(*reinterpret_cast<unsigned long long*>(&r))
        : "l"(*reinterpret_cast<unsigned long long*>(&a)),
          "l"(*reinterpret_cast<unsigned long long*>(&b)),
          "l"(*reinterpret_cast<unsigned long long*>(&c)));
    return r;
}

// ---------------- cp.async helpers ----------------
__device__ __forceinline__ unsigned smem_u32p(const void* p) {
    return (unsigned)__cvta_generic_to_shared(p);
}
#define CP_ASYNC16(dst_u32, src_ptr) \
    asm volatile("cp.async.cg.shared.global [%0], [%1], 16;" \
                 :: "r"(dst_u32), "l"(src_ptr))
#define CP_COMMIT() asm volatile("cp.async.commit_group;" ::: "memory")
#define CP_WAIT0()  asm volatile("cp.async.wait_group 0;" ::: "memory")

// ---------------- device scratch ----------------
__device__ float g_src [ROWS * HD];
__device__ float g_tgt [ROWS * HD];
__device__ float g_skip[ROWS * HD];
__device__ float g_asrc[BSZ * HEADS * NN];
__device__ float g_atgt[BSZ * HEADS * NN];

// ---------------------------------------------------------------------------
// K1: three projections (double-buffered) + fused adj copy.
// z<3: 64x64 GEMM tiles; z==3: adj int4->float4 copy. Grid (8,16,4), 128 thr.
// ---------------------------------------------------------------------------
#define APITCH 68
#define BPITCH 68

__global__ void __launch_bounds__(128) gemm3_kernel(
    const float* __restrict__ X,
    const float* __restrict__ Wsrc,
    const float* __restrict__ Wtgt,
    const float* __restrict__ Wskip,
    const float* __restrict__ scoring,
    const int4*  __restrict__ adj4,
    float4*      __restrict__ adj_dst,
    int n4)
{
    const int z = blockIdx.z;
    const int t = threadIdx.x;

    if (z == 3) {
        const int bid = blockIdx.y * 8 + blockIdx.x;
#pragma unroll
        for (int i = 0; i < 8; i++) {
            int idx = bid * 128 + t + i * 16384;
            if (idx < n4) {
                int4 v = adj4[idx];
                adj_dst[idx] = make_float4((float)v.x, (float)v.y,
                                           (float)v.z, (float)v.w);
            }
        }
        return;
    }

    __shared__ __align__(16) float As[2][32 * APITCH];
    __shared__ __align__(16) float Bs[2][32 * BPITCH];
    __shared__ float sh_sv[64];

    const float* W = (z == 0) ? Wsrc : (z == 1) ? Wtgt : Wskip;
    float* C = (z == 0) ? g_src : (z == 1) ? g_tgt : g_skip;

    const int rowBase = blockIdx.y * 64;
    const int colBase = blockIdx.x * 64;

    const int nG = t >> 4;            // 0..7 -> 8 rows (4 n-pairs)
    const int dG = t & 15;            // 0..15 -> 4 cols
    const int r0 = nG * 8;
    const int d0 = dG * 4;

    const int ak = t & 31;
    const int an = t >> 5;
    const int bk = t >> 4;
    const int bd = (t & 15) * 4;

    if (t < 16)
        *(float4*)&sh_sv[t * 4] = *(const float4*)&scoring[colBase + t * 4];

    F2 acc[4][4];
#pragma unroll
    for (int p = 0; p < 4; p++)
#pragma unroll
        for (int j = 0; j < 4; j++) acc[p][j] = {0.f, 0.f};

    float  aR[16];
    float4 bR[4];

    // preload slab 0 and stage into buffer 0
#pragma unroll
    for (int i = 0; i < 16; i++)
        aR[i] = X[(size_t)(rowBase + an + 4 * i) * DIN + ak];
#pragma unroll
    for (int i = 0; i < 4; i++)
        bR[i] = *(const float4*)&W[(size_t)(bk + 8 * i) * HD + colBase + bd];
#pragma unroll
    for (int i = 0; i < 16; i++)
        As[0][ak * APITCH + an + 4 * i] = aR[i];
#pragma unroll
    for (int i = 0; i < 4; i++)
        *(float4*)&Bs[0][(bk + 8 * i) * BPITCH + bd] = bR[i];

    for (int s = 0; s < 8; s++) {
        if (s < 7) {
            const int k0 = (s + 1) * 32;
#pragma unroll
            for (int i = 0; i < 16; i++)
                aR[i] = X[(size_t)(rowBase + an + 4 * i) * DIN + k0 + ak];
#pragma unroll
            for (int i = 0; i < 4; i++)
                bR[i] = *(const float4*)&W[(size_t)(k0 + bk + 8 * i) * HD + colBase + bd];
        }
        __syncthreads();
        const float* Ab = As[s & 1];
        const float* Bb = Bs[s & 1];

#pragma unroll
        for (int k = 0; k < 32; k++) {
            float4 a01 = *(const float4*)&Ab[k * APITCH + r0];
            float4 a23 = *(const float4*)&Ab[k * APITCH + r0 + 4];
            float4 b   = *(const float4*)&Bb[k * BPITCH + d0];
            F2 ap[4] = {{a01.x, a01.y}, {a01.z, a01.w}, {a23.x, a23.y}, {a23.z, a23.w}};
            F2 bb[4] = {{b.x, b.x}, {b.y, b.y}, {b.z, b.z}, {b.w, b.w}};
#pragma unroll
            for (int p = 0; p < 4; p++)
#pragma unroll
                for (int j = 0; j < 4; j++)
                    acc[p][j] = f2fma(ap[p], bb[j], acc[p][j]);
        }

        if (s < 7) {
            float* An = As[(s + 1) & 1];
            float* Bn = Bs[(s + 1) & 1];
#pragma unroll
            for (int i = 0; i < 16; i++)
                An[ak * APITCH + an + 4 * i] = aR[i];
#pragma unroll
            for (int i = 0; i < 4; i++)
                *(float4*)&Bn[(bk + 8 * i) * BPITCH + bd] = bR[i];
        }
    }

#pragma unroll
    for (int p = 0; p < 4; p++) {
        float4 lo = make_float4(acc[p][0].x, acc[p][1].x, acc[p][2].x, acc[p][3].x);
        float4 hi = make_float4(acc[p][0].y, acc[p][1].y, acc[p][2].y, acc[p][3].y);
        *(float4*)&C[(size_t)(rowBase + r0 + 2 * p)     * HD + colBase + d0] = lo;
        *(float4*)&C[(size_t)(rowBase + r0 + 2 * p + 1) * HD + colBase + d0] = hi;
    }

    if (z < 2) {
        const float s0 = sh_sv[d0], s1 = sh_sv[d0 + 1],
                    s2 = sh_sv[d0 + 2], s3 = sh_sv[d0 + 3];
        float part[8];
#pragma unroll
        for (int p = 0; p < 4; p++) {
            part[2 * p]     = acc[p][0].x * s0 + acc[p][1].x * s1
                            + acc[p][2].x * s2 + acc[p][3].x * s3;
            part[2 * p + 1] = acc[p][0].y * s0 + acc[p][1].y * s1
                            + acc[p][2].y * s2 + acc[p][3].y * s3;
        }
#pragma unroll
        for (int o = 1; o <= 8; o <<= 1)
#pragma unroll
            for (int i = 0; i < 8; i++)
                part[i] += __shfl_xor_sync(0xffffffffu, part[i], o);
        if (dG == 0) {
            float* dst = (z == 0) ? g_asrc : g_atgt;
            const int hh = blockIdx.x;
#pragma unroll
            for (int i = 0; i < 8; i++) {
                int rG = rowBase + r0 + i;
                dst[((rG >> 9) * HEADS + hh) * NN + (rG & (NN - 1))] = part[i];
            }
        }
    }
}

// ---------------------------------------------------------------------------
// K2: fused scores + mask + softmax + aggregation + skip + bias + ELU
// Block = (16 query rows, head, batch); 256 threads; grid (32,8,2)=512.
// cp.async double-buffered staging; adj prefetched to a bitmask in prologue;
// phase-2 prob loads as float4 (PPITCH=520, 16B aligned).
// ---------------------------------------------------------------------------
#define PPITCH 520
#define TPITCH 12                 // 16B-aligned rows for float4 LDS
#define STG_SZ (512 * TPITCH)     // 6144 floats per buffer
#define VPITCH 68
#define VBUF_SZ (64 * VPITCH)     // 4352 floats per buffer

__global__ void __launch_bounds__(256, 2) attn_kernel(
    const int*   __restrict__ adj,
    const float* __restrict__ scoring,
    const float* __restrict__ bias,
    float*       __restrict__ out)
{
    __shared__ __align__(16) float BUF [2 * STG_SZ];   // staging -> probs -> overlay
    __shared__ __align__(16) float VBUF[2 * VBUF_SZ];
    __shared__ __align__(16) float sh_src[16 * 64];
    __shared__ float sh_atgt[512];
    __shared__ __align__(16) float sh_s[64];
    __shared__ float sh_asrc[16];
    __shared__ float sh_inv[16];
    __shared__ float REDM[4][2][4];
    __shared__ float REDS[4][2][4];

    const int t  = threadIdx.x;
    const int bn = blockIdx.x * 16;
    const int h  = blockIdx.y;
    const int b  = blockIdx.z;
    const int bh = b * HEADS + h;

    const int nG = t >> 6;          // 0..3 (4 n each)
    const int mG = t & 63;          // m = mG + 64*mm
    const int wg = (t >> 5) & 1;

    // ---- kick off chunk-0 staging via cp.async (fresh smem, no hazard) ----
    const unsigned bufBase = smem_u32p(BUF);
#pragma unroll
    for (int q = 0; q < 4; q++) {
        int f4 = t + 256 * q;
        int row = f4 >> 1, half = f4 & 1;
        CP_ASYNC16(bufBase + (unsigned)(row * TPITCH + half * 4) * 4u,
                   &g_tgt[(size_t)(b * NN + row) * HD + h * 64 + half * 4]);
    }
    CP_COMMIT();

    // ---- adj bitmask (32 LDG issued early; latency overlaps staging+compute) ----
    unsigned amask = 0;
#pragma unroll
    for (int mm = 0; mm < 8; mm++)
#pragma unroll
        for (int i = 0; i < 4; i++) {
            int m = mG + 64 * mm;
            int av = adj[(size_t)(b * NN + bn + nG * 4 + i) * NN + m];
            amask |= (av == 0) ? (1u << (mm * 4 + i)) : 0u;
        }

    // ---- prologue loads ----
    if (t < 16) {
        float4 v = *(const float4*)&scoring[h * 64 + t * 4];
        v.x *= (1.f - ALPHA); v.y *= (1.f - ALPHA);
        v.z *= (1.f - ALPHA); v.w *= (1.f - ALPHA);
        *(float4*)&sh_s[t * 4] = v;
        sh_asrc[t] = g_asrc[bh * NN + bn + t];
    }
    {
        int r = t >> 4, c = t & 15;
        *(float4*)&sh_src[r * 64 + c * 4] =
            *(const float4*)&g_src[(size_t)(b * NN + bn + r) * HD + h * 64 + c * 4];
    }
    sh_atgt[t]       = g_atgt[bh * NN + t];
    sh_atgt[t + 256] = g_atgt[bh * NN + t + 256];

    // ---- phase 1: scores (4n x 8m), cp.async double-buffered d-chunks of 8 ----
    F2 acc[4][8];
#pragma unroll
    for (int i = 0; i < 4; i++)
#pragma unroll
        for (int mm = 0; mm < 8; mm++) acc[i][mm] = {0.f, 0.f};

    for (int chunk = 0; chunk < 8; chunk++) {
        CP_WAIT0();
        __syncthreads();   // cur buffer visible; all done reading other buffer

        if (chunk < 7) {
            const int c8 = (chunk + 1) * 8;
            const unsigned nb = bufBase + (unsigned)(((chunk + 1) & 1) * STG_SZ) * 4u;
#pragma unroll
            for (int q = 0; q < 4; q++) {
                int f4 = t + 256 * q;
                int row = f4 >> 1, half = f4 & 1;
                CP_ASYNC16(nb + (unsigned)(row * TPITCH + half * 4) * 4u,
                           &g_tgt[(size_t)(b * NN + row) * HD + h * 64 + c8 + half * 4]);
            }
            CP_COMMIT();
        }
        const float* ST = &BUF[(chunk & 1) * STG_SZ];

#pragma unroll
        for (int j4 = 0; j4 < 2; j4++) {
            float4 s4 = *(const float4*)&sh_s[chunk * 8 + j4 * 4];
            F2 sjA = {s4.x, s4.y}, sjB = {s4.z, s4.w};
            float4 sv[4];
#pragma unroll
            for (int i = 0; i < 4; i++)
                sv[i] = *(const float4*)&sh_src[(nG * 4 + i) * 64 + chunk * 8 + j4 * 4];
#pragma unroll
            for (int mm = 0; mm < 8; mm++) {
                float4 tv4 = *(const float4*)&ST[(mG + 64 * mm) * TPITCH + j4 * 4];
                F2 tvA = {tv4.x, tv4.y}, tvB = {tv4.z, tv4.w};
#pragma unroll
                for (int i = 0; i < 4; i++) {
                    F2 uA = f2add(F2{sv[i].x, sv[i].y}, tvA);
                    uA.x = fmaxf(uA.x, 0.f);
                    uA.y = fmaxf(uA.y, 0.f);
                    acc[i][mm] = f2fma(sjA, uA, acc[i][mm]);
                    F2 uB = f2add(F2{sv[i].z, sv[i].w}, tvB);
                    uB.x = fmaxf(uB.x, 0.f);
                    uB.y = fmaxf(uB.y, 0.f);
                    acc[i][mm] = f2fma(sjB, uB, acc[i][mm]);
                }
            }
        }
    }

    // ---- finalize scores (in acc[][].x): alpha-term + mask (bitmask); max ----
    float a_n[4];
#pragma unroll
    for (int i = 0; i < 4; i++) a_n[i] = sh_asrc[nG * 4 + i];

    float rm[4] = {-3.4e38f, -3.4e38f, -3.4e38f, -3.4e38f};
#pragma unroll
    for (int mm = 0; mm < 8; mm++) {
        const int m = mG + 64 * mm;
        const float bm = sh_atgt[m];
#pragma unroll
        for (int i = 0; i < 4; i++) {
            float s = acc[i][mm].x + acc[i][mm].y;
            s = fmaf(ALPHA, a_n[i] + bm, s);
            s = (amask & (1u << (mm * 4 + i))) ? s - 1.0e9f : s;
            acc[i][mm].x = s;
            rm[i] = fmaxf(rm[i], s);
        }
    }
#pragma unroll
    for (int i = 0; i < 4; i++)
#pragma unroll
        for (int o = 16; o; o >>= 1)
            rm[i] = fmaxf(rm[i], __shfl_xor_sync(0xffffffffu, rm[i], o));
    if ((t & 31) == 0)
#pragma unroll
        for (int i = 0; i < 4; i++) REDM[nG][wg][i] = rm[i];
    __syncthreads();   // staging reads done -> BUF reusable as prob buffer
#pragma unroll
    for (int i = 0; i < 4; i++) rm[i] = fmaxf(REDM[nG][0][i], REDM[nG][1][i]);

    // ---- exp -> probs to BUF; sum ----
    float ps[4] = {0.f, 0.f, 0.f, 0.f};
#pragma unroll
    for (int mm = 0; mm < 8; mm++) {
        const int m = mG + 64 * mm;
#pragma unroll
        for (int i = 0; i < 4; i++) {
            float e = __expf(acc[i][mm].x - rm[i]);
            BUF[(nG * 4 + i) * PPITCH + m] = e;
            ps[i] += e;
        }
    }
#pragma unroll
    for (int i = 0; i < 4; i++)
#pragma unroll
        for (int o = 16; o; o >>= 1)
            ps[i] += __shfl_xor_sync(0xffffffffu, ps[i], o);
    if ((t & 31) == 0)
#pragma unroll
        for (int i = 0; i < 4; i++) REDS[nG][wg][i] = ps[i];
    __syncthreads();
    if (t < 16)
        sh_inv[t] = 1.f / (REDS[t >> 2][0][t & 3] + REDS[t >> 2][1][t & 3]);

    // ---- phase 2: aggregation (8 m-groups, 4n x 8d), cp.async double-buffered ----
    const int g    = t >> 5;        // 0..7
    const int l    = t & 31;
    const int nSub = l >> 3;        // 0..3 (4 n each)
    const int dSub = l & 7;         // 0..7 (8 floats each)

    F2 acc2[4][4];
#pragma unroll
    for (int i = 0; i < 4; i++)
#pragma unroll
        for (int j = 0; j < 4; j++) acc2[i][j] = {0.f, 0.f};

    const unsigned vbufBase = smem_u32p(VBUF);
#pragma unroll
    for (int q = 0; q < 4; q++) {
        int f4 = t + 256 * q;
        int row = f4 >> 4, c = f4 & 15;
        CP_ASYNC16(vbufBase + (unsigned)(row * VPITCH + c * 4) * 4u,
                   &g_src[(size_t)(b * NN + row) * HD + h * 64 + c * 4]);
    }
    CP_COMMIT();

    for (int tile = 0; tile < 8; tile++) {
        CP_WAIT0();
        __syncthreads();

        if (tile < 7) {
            const unsigned nb = vbufBase + (unsigned)(((tile + 1) & 1) * VBUF_SZ) * 4u;
#pragma unroll
            for (int q = 0; q < 4; q++) {
                int f4 = t + 256 * q;
                int row = f4 >> 4, c = f4 & 15;
                CP_ASYNC16(nb + (unsigned)(row * VPITCH + c * 4) * 4u,
                           &g_src[(size_t)(b * NN + (tile + 1) * 64 + row) * HD + h * 64 + c * 4]);
            }
            CP_COMMIT();
        }
        const float* VB = &VBUF[(tile & 1) * VBUF_SZ];

        // prob vectors: 2 float4 per i (8 consecutive m), broadcast across dSub
        float4 pv[4][2];
#pragma unroll
        for (int i = 0; i < 4; i++) {
            const int base = (nSub * 4 + i) * PPITCH + tile * 64 + g * 8;
            pv[i][0] = *(const float4*)&BUF[base];
            pv[i][1] = *(const float4*)&BUF[base + 4];
        }

#pragma unroll
        for (int mm = 0; mm < 8; mm++) {
            const int mloc = g * 8 + mm;
            float4 v01 = *(const float4*)&VB[mloc * VPITCH + dSub * 8];
            float4 v23 = *(const float4*)&VB[mloc * VPITCH + dSub * 8 + 4];
            F2 vv[4] = {{v01.x, v01.y}, {v01.z, v01.w}, {v23.x, v23.y}, {v23.z, v23.w}};
#pragma unroll
            for (int i = 0; i < 4; i++) {
                const float* pf = (const float*)&pv[i][mm >> 2];
                float p = pf[mm & 3];
                F2 pp = {p, p};
#pragma unroll
                for (int j = 0; j < 4; j++)
                    acc2[i][j] = f2fma(pp, vv[j], acc2[i][j]);
            }
        }
    }

    // ---- two-stage reduction over 8 groups (probs dead -> overlay in BUF) ----
    __syncthreads();
    if (g >= 4) {
#pragma unroll
        for (int i = 0; i < 4; i++)
#pragma unroll
            for (int j = 0; j < 4; j++)
                *(F2*)&BUF[(g - 4) * 1024 + (nSub * 4 + i) * 64 + dSub * 8 + 2 * j]
                    = acc2[i][j];
    }
    __syncthreads();
    if (g < 4) {
#pragma unroll
        for (int i = 0; i < 4; i++)
#pragma unroll
            for (int j = 0; j < 4; j++) {
                F2 o = *(const F2*)&BUF[g * 1024 + (nSub * 4 + i) * 64 + dSub * 8 + 2 * j];
                acc2[i][j] = f2add(acc2[i][j], o);
                *(F2*)&BUF[g * 1024 + (nSub * 4 + i) * 64 + dSub * 8 + 2 * j] = acc2[i][j];
            }
    }
    __syncthreads();

    // ---- final reduce + epilogue (256 threads, 4 outputs each) ----
    {
        const int oIdx = t * 4;
        const int n = oIdx >> 6, d = oIdx & 63;
        float4 s = make_float4(0.f, 0.f, 0.f, 0.f);
#pragma unroll
        for (int g2 = 0; g2 < 4; g2++) {
            float4 r = *(const float4*)&BUF[g2 * 1024 + oIdx];
            s.x += r.x; s.y += r.y; s.z += r.z; s.w += r.w;
        }
        const float inv = sh_inv[n];
        const size_t off = (size_t)(b * NN + bn + n) * HD + h * 64 + d;
        float4 sk = *(const float4*)&g_skip[off];
        float4 bi = *(const float4*)&bias[h * 64 + d];
        float4 o;
        o.x = fmaf(s.x, inv, sk.x + bi.x);
        o.y = fmaf(s.y, inv, sk.y + bi.y);
        o.z = fmaf(s.z, inv, sk.z + bi.z);
        o.w = fmaf(s.w, inv, sk.w + bi.w);
        o.x = (o.x > 0.f) ? o.x : expm1f(o.x);
        o.y = (o.y > 0.f) ? o.y : expm1f(o.y);
        o.z = (o.z > 0.f) ? o.z : expm1f(o.z);
        o.w = (o.w > 0.f) ? o.w : expm1f(o.w);
        *(float4*)&out[off] = o;
    }
}

// ---------------------------------------------------------------------------
// Tail copy (only if extra not divisible by 4)
// ---------------------------------------------------------------------------
__global__ void copy_adj_tail_kernel(
    const int* __restrict__ adj, float* __restrict__ dst, int off, int n)
{
    int i = blockIdx.x * 256 + threadIdx.x;
    if (i < n) dst[off + i] = (float)adj[off + i];
}

extern "C" void kernel_launch(void* const* d_in, const int* in_sizes, int n_in,
                              void* d_out, int out_size)
{
    const float* x       = (const float*)d_in[0];
    const int*   adj     = (const int*)  d_in[1];
    const float* Wsrc    = (const float*)d_in[2];
    const float* Wtgt    = (const float*)d_in[3];
    const float* Wskip   = (const float*)d_in[4];
    const float* scoring = (const float*)d_in[5];
    const float* bias    = (const float*)d_in[6];
    float* out = (float*)d_out;

    const int main_elems = ROWS * HD;               // 524288
    int extra = out_size - main_elems;
    if (extra < 0) extra = 0;
    const int adj_elems = BSZ * NN * NN;            // 524288
    if (extra > adj_elems) extra = adj_elems;
    int n4 = extra >> 2;

    gemm3_kernel<<<dim3(HD / 64, ROWS / 64, 4), 128>>>(
        x, Wsrc, Wtgt, Wskip, scoring,
        (const int4*)adj, (float4*)(out + main_elems), n4);
    attn_kernel<<<dim3(NN / 16, HEADS, BSZ), 256>>>(adj, scoring, bias, out);

    int rem = extra - (n4 << 2);
    if (rem > 0)
        copy_adj_tail_kernel<<<1, 256>>>(adj, out + main_elems, n4 << 2, rem);
}

// round 15
// speedup vs baseline: 1.0702x; 1.0702x over previous
#include <cuda_runtime.h>
#include <math.h>

#define BSZ   2
#define NN    512
#define DIN   256
#define HEADS 8
#define DOUT  64
#define HD    512
#define ROWS  1024
#define ALPHA 0.2f

// ---------------- packed fp32x2 helpers (Blackwell FADD2/FFMA2) ----------------
struct __align__(8) F2 { float x, y; };

__device__ __forceinline__ F2 f2add(F2 a, F2 b) {
    F2 r;
    asm("add.rn.f32x2 %0, %1, %2;"
        : "=l"(*reinterpret_cast<unsigned long long*>(&r))
        : "l"(*reinterpret_cast<unsigned long long*>(&a)),
          "l"(*reinterpret_cast<unsigned long long*>(&b)));
    return r;
}
__device__ __forceinline__ F2 f2fma(F2 a, F2 b, F2 c) {
    F2 r;
    asm("fma.rn.f32x2 %0, %1, %2, %3;"
        : "=l"(*reinterpret_cast<unsigned long long*>(&r))
        : "l"(*reinterpret_cast<unsigned long long*>(&a)),
          "l"(*reinterpret_cast<unsigned long long*>(&b)),
          "l"(*reinterpret_cast<unsigned long long*>(&c)));
    return r;
}

// ---------------- cp.async helpers ----------------
__device__ __forceinline__ unsigned smem_u32p(const void* p) {
    return (unsigned)__cvta_generic_to_shared(p);
}
#define CP_ASYNC16(dst_u32, src_ptr) \
    asm volatile("cp.async.cg.shared.global [%0], [%1], 16;" \
                 :: "r"(dst_u32), "l"(src_ptr))
#define CP_COMMIT() asm volatile("cp.async.commit_group;" ::: "memory")
#define CP_WAIT0()  asm volatile("cp.async.wait_group 0;" ::: "memory")

// ---------------- device scratch ----------------
__device__ float g_src [ROWS * HD];
__device__ float g_tgt [ROWS * HD];
__device__ float g_skip[ROWS * HD];
__device__ float g_asrc[BSZ * HEADS * NN];
__device__ float g_atgt[BSZ * HEADS * NN];

// ---------------------------------------------------------------------------
// K1: three projections + fused adj copy.
// z<3: 64x64 GEMM tiles, k-slab 64 (4 slabs), double-buffered, APITCH=76
// (4-way A-store conflicts instead of 8-way). z==3: adj copy.
// Grid (8,16,4), 128 threads.
// ---------------------------------------------------------------------------
#define APITCH 76
#define BPITCH 68

__global__ void __launch_bounds__(128) gemm3_kernel(
    const float* __restrict__ X,
    const float* __restrict__ Wsrc,
    const float* __restrict__ Wtgt,
    const float* __restrict__ Wskip,
    const float* __restrict__ scoring,
    const int4*  __restrict__ adj4,
    float4*      __restrict__ adj_dst,
    int n4)
{
    const int z = blockIdx.z;
    const int t = threadIdx.x;

    if (z == 3) {
        const int bid = blockIdx.y * 8 + blockIdx.x;
#pragma unroll
        for (int i = 0; i < 8; i++) {
            int idx = bid * 128 + t + i * 16384;
            if (idx < n4) {
                int4 v = adj4[idx];
                adj_dst[idx] = make_float4((float)v.x, (float)v.y,
                                           (float)v.z, (float)v.w);
            }
        }
        return;
    }

    __shared__ __align__(16) float As[2][64 * APITCH];  // [k][n]
    __shared__ __align__(16) float Bs[2][64 * BPITCH];  // [k][d]
    __shared__ float sh_sv[64];

    const float* W = (z == 0) ? Wsrc : (z == 1) ? Wtgt : Wskip;
    float* C = (z == 0) ? g_src : (z == 1) ? g_tgt : g_skip;

    const int rowBase = blockIdx.y * 64;
    const int colBase = blockIdx.x * 64;

    const int nG = t >> 4;            // 0..7 -> 8 rows (4 n-pairs)
    const int dG = t & 15;            // 0..15 -> 4 cols
    const int r0 = nG * 8;
    const int d0 = dG * 4;

    // loaders (slab of 64 k)
    const int ak = t & 63;            // A: k lane (coalesced over 64)
    const int an = t >> 6;            // A: n base 0..1 (+2i, i<32)
    const int bk = t >> 4;            // B: k base 0..7 (+8q, q<8)
    const int bd = (t & 15) * 4;      // B: float4 col

    if (t < 16)
        *(float4*)&sh_sv[t * 4] = *(const float4*)&scoring[colBase + t * 4];

    F2 acc[4][4];
#pragma unroll
    for (int p = 0; p < 4; p++)
#pragma unroll
        for (int j = 0; j < 4; j++) acc[p][j] = {0.f, 0.f};

    float  aR[32];
    float4 bR[8];

    // preload slab 0 and stage into buffer 0
#pragma unroll
    for (int i = 0; i < 32; i++)
        aR[i] = X[(size_t)(rowBase + an + 2 * i) * DIN + ak];
#pragma unroll
    for (int q = 0; q < 8; q++)
        bR[q] = *(const float4*)&W[(size_t)(bk + 8 * q) * HD + colBase + bd];
#pragma unroll
    for (int i = 0; i < 32; i++)
        As[0][ak * APITCH + an + 2 * i] = aR[i];
#pragma unroll
    for (int q = 0; q < 8; q++)
        *(float4*)&Bs[0][(bk + 8 * q) * BPITCH + bd] = bR[q];

    for (int s = 0; s < 4; s++) {
        if (s < 3) {
            const int k0 = (s + 1) * 64;
#pragma unroll
            for (int i = 0; i < 32; i++)
                aR[i] = X[(size_t)(rowBase + an + 2 * i) * DIN + k0 + ak];
#pragma unroll
            for (int q = 0; q < 8; q++)
                bR[q] = *(const float4*)&W[(size_t)(k0 + bk + 8 * q) * HD + colBase + bd];
        }
        __syncthreads();
        const float* Ab = As[s & 1];
        const float* Bb = Bs[s & 1];

#pragma unroll
        for (int k = 0; k < 64; k++) {
            float4 a01 = *(const float4*)&Ab[k * APITCH + r0];
            float4 a23 = *(const float4*)&Ab[k * APITCH + r0 + 4];
            float4 b   = *(const float4*)&Bb[k * BPITCH + d0];
            F2 ap[4] = {{a01.x, a01.y}, {a01.z, a01.w}, {a23.x, a23.y}, {a23.z, a23.w}};
            F2 bb[4] = {{b.x, b.x}, {b.y, b.y}, {b.z, b.z}, {b.w, b.w}};
#pragma unroll
            for (int p = 0; p < 4; p++)
#pragma unroll
                for (int j = 0; j < 4; j++)
                    acc[p][j] = f2fma(ap[p], bb[j], acc[p][j]);
        }

        if (s < 3) {
            float* An = As[(s + 1) & 1];
            float* Bn = Bs[(s + 1) & 1];
#pragma unroll
            for (int i = 0; i < 32; i++)
                An[ak * APITCH + an + 2 * i] = aR[i];
#pragma unroll
            for (int q = 0; q < 8; q++)
                *(float4*)&Bn[(bk + 8 * q) * BPITCH + bd] = bR[q];
        }
    }

#pragma unroll
    for (int p = 0; p < 4; p++) {
        float4 lo = make_float4(acc[p][0].x, acc[p][1].x, acc[p][2].x, acc[p][3].x);
        float4 hi = make_float4(acc[p][0].y, acc[p][1].y, acc[p][2].y, acc[p][3].y);
        *(float4*)&C[(size_t)(rowBase + r0 + 2 * p)     * HD + colBase + d0] = lo;
        *(float4*)&C[(size_t)(rowBase + r0 + 2 * p + 1) * HD + colBase + d0] = hi;
    }

    if (z < 2) {
        const float s0 = sh_sv[d0], s1 = sh_sv[d0 + 1],
                    s2 = sh_sv[d0 + 2], s3 = sh_sv[d0 + 3];
        float part[8];
#pragma unroll
        for (int p = 0; p < 4; p++) {
            part[2 * p]     = acc[p][0].x * s0 + acc[p][1].x * s1
                            + acc[p][2].x * s2 + acc[p][3].x * s3;
            part[2 * p + 1] = acc[p][0].y * s0 + acc[p][1].y * s1
                            + acc[p][2].y * s2 + acc[p][3].y * s3;
        }
#pragma unroll
        for (int o = 1; o <= 8; o <<= 1)
#pragma unroll
            for (int i = 0; i < 8; i++)
                part[i] += __shfl_xor_sync(0xffffffffu, part[i], o);
        if (dG == 0) {
            float* dst = (z == 0) ? g_asrc : g_atgt;
            const int hh = blockIdx.x;
#pragma unroll
            for (int i = 0; i < 8; i++) {
                int rG = rowBase + r0 + i;
                dst[((rG >> 9) * HEADS + hh) * NN + (rG & (NN - 1))] = part[i];
            }
        }
    }
}

// ---------------------------------------------------------------------------
// K2: fused scores + mask + softmax + aggregation + skip + bias + ELU
// (EXACT round-12 version: measured 65.9us / 88.5 total.)
// ---------------------------------------------------------------------------
#define PPITCH 517
#define TPITCH 12                 // 16B-aligned rows for float4 LDS
#define STG_SZ (512 * TPITCH)     // 6144 floats per buffer
#define VPITCH 68
#define VBUF_SZ (64 * VPITCH)     // 4352 floats per buffer

__global__ void __launch_bounds__(256, 2) attn_kernel(
    const int*   __restrict__ adj,
    const float* __restrict__ scoring,
    const float* __restrict__ bias,
    float*       __restrict__ out)
{
    __shared__ __align__(16) float BUF [2 * STG_SZ];   // staging -> probs -> overlay
    __shared__ __align__(16) float VBUF[2 * VBUF_SZ];
    __shared__ __align__(16) float sh_src[16 * 64];
    __shared__ float sh_atgt[512];
    __shared__ __align__(16) float sh_s[64];
    __shared__ float sh_asrc[16];
    __shared__ float sh_inv[16];
    __shared__ float REDM[4][2][4];
    __shared__ float REDS[4][2][4];

    const int t  = threadIdx.x;
    const int bn = blockIdx.x * 16;
    const int h  = blockIdx.y;
    const int b  = blockIdx.z;
    const int bh = b * HEADS + h;

    const int nG = t >> 6;          // 0..3 (4 n each)
    const int mG = t & 63;          // m = mG + 64*mm
    const int wg = (t >> 5) & 1;

    // ---- kick off chunk-0 staging via cp.async (fresh smem, no hazard) ----
    const unsigned bufBase = smem_u32p(BUF);
#pragma unroll
    for (int q = 0; q < 4; q++) {
        int f4 = t + 256 * q;
        int row = f4 >> 1, half = f4 & 1;
        CP_ASYNC16(bufBase + (unsigned)(row * TPITCH + half * 4) * 4u,
                   &g_tgt[(size_t)(b * NN + row) * HD + h * 64 + half * 4]);
    }
    CP_COMMIT();

    // ---- prologue loads ----
    if (t < 16) {
        float4 v = *(const float4*)&scoring[h * 64 + t * 4];
        v.x *= (1.f - ALPHA); v.y *= (1.f - ALPHA);
        v.z *= (1.f - ALPHA); v.w *= (1.f - ALPHA);
        *(float4*)&sh_s[t * 4] = v;
        sh_asrc[t] = g_asrc[bh * NN + bn + t];
    }
    {
        int r = t >> 4, c = t & 15;
        *(float4*)&sh_src[r * 64 + c * 4] =
            *(const float4*)&g_src[(size_t)(b * NN + bn + r) * HD + h * 64 + c * 4];
    }
    sh_atgt[t]       = g_atgt[bh * NN + t];
    sh_atgt[t + 256] = g_atgt[bh * NN + t + 256];

    // ---- phase 1: scores (4n x 8m), cp.async double-buffered d-chunks of 8 ----
    F2 acc[4][8];
#pragma unroll
    for (int i = 0; i < 4; i++)
#pragma unroll
        for (int mm = 0; mm < 8; mm++) acc[i][mm] = {0.f, 0.f};

    for (int chunk = 0; chunk < 8; chunk++) {
        CP_WAIT0();
        __syncthreads();   // cur buffer visible to all; all done reading next buffer

        if (chunk < 7) {
            const int c8 = (chunk + 1) * 8;
            const unsigned nb = bufBase + (unsigned)(((chunk + 1) & 1) * STG_SZ) * 4u;
#pragma unroll
            for (int q = 0; q < 4; q++) {
                int f4 = t + 256 * q;
                int row = f4 >> 1, half = f4 & 1;
                CP_ASYNC16(nb + (unsigned)(row * TPITCH + half * 4) * 4u,
                           &g_tgt[(size_t)(b * NN + row) * HD + h * 64 + c8 + half * 4]);
            }
            CP_COMMIT();
        }
        const float* ST = &BUF[(chunk & 1) * STG_SZ];

#pragma unroll
        for (int j4 = 0; j4 < 2; j4++) {
            float4 s4 = *(const float4*)&sh_s[chunk * 8 + j4 * 4];
            F2 sjA = {s4.x, s4.y}, sjB = {s4.z, s4.w};
            float4 sv[4];
#pragma unroll
            for (int i = 0; i < 4; i++)
                sv[i] = *(const float4*)&sh_src[(nG * 4 + i) * 64 + chunk * 8 + j4 * 4];
#pragma unroll
            for (int mm = 0; mm < 8; mm++) {
                float4 tv4 = *(const float4*)&ST[(mG + 64 * mm) * TPITCH + j4 * 4];
                F2 tvA = {tv4.x, tv4.y}, tvB = {tv4.z, tv4.w};
#pragma unroll
                for (int i = 0; i < 4; i++) {
                    F2 uA = f2add(F2{sv[i].x, sv[i].y}, tvA);
                    uA.x = fmaxf(uA.x, 0.f);
                    uA.y = fmaxf(uA.y, 0.f);
                    acc[i][mm] = f2fma(sjA, uA, acc[i][mm]);
                    F2 uB = f2add(F2{sv[i].z, sv[i].w}, tvB);
                    uB.x = fmaxf(uB.x, 0.f);
                    uB.y = fmaxf(uB.y, 0.f);
                    acc[i][mm] = f2fma(sjB, uB, acc[i][mm]);
                }
            }
        }
    }

    // ---- finalize scores (in acc[][].x): alpha-term + mask; track max ----
    float a_n[4];
#pragma unroll
    for (int i = 0; i < 4; i++) a_n[i] = sh_asrc[nG * 4 + i];

    float rm[4] = {-3.4e38f, -3.4e38f, -3.4e38f, -3.4e38f};
#pragma unroll
    for (int mm = 0; mm < 8; mm++) {
        const int m = mG + 64 * mm;
        const float bm = sh_atgt[m];
#pragma unroll
        for (int i = 0; i < 4; i++) {
            float s = acc[i][mm].x + acc[i][mm].y;
            s = fmaf(ALPHA, a_n[i] + bm, s);
            int av = adj[(size_t)(b * NN + bn + nG * 4 + i) * NN + m];
            s = (av == 0) ? s - 1.0e9f : s;
            acc[i][mm].x = s;
            rm[i] = fmaxf(rm[i], s);
        }
    }
#pragma unroll
    for (int i = 0; i < 4; i++)
#pragma unroll
        for (int o = 16; o; o >>= 1)
            rm[i] = fmaxf(rm[i], __shfl_xor_sync(0xffffffffu, rm[i], o));
    if ((t & 31) == 0)
#pragma unroll
        for (int i = 0; i < 4; i++) REDM[nG][wg][i] = rm[i];
    __syncthreads();   // staging reads done -> BUF reusable as prob buffer
#pragma unroll
    for (int i = 0; i < 4; i++) rm[i] = fmaxf(REDM[nG][0][i], REDM[nG][1][i]);

    // ---- exp -> probs to BUF; sum ----
    float ps[4] = {0.f, 0.f, 0.f, 0.f};
#pragma unroll
    for (int mm = 0; mm < 8; mm++) {
        const int m = mG + 64 * mm;
#pragma unroll
        for (int i = 0; i < 4; i++) {
            float e = __expf(acc[i][mm].x - rm[i]);
            BUF[(nG * 4 + i) * PPITCH + m] = e;
            ps[i] += e;
        }
    }
#pragma unroll
    for (int i = 0; i < 4; i++)
#pragma unroll
        for (int o = 16; o; o >>= 1)
            ps[i] += __shfl_xor_sync(0xffffffffu, ps[i], o);
    if ((t & 31) == 0)
#pragma unroll
        for (int i = 0; i < 4; i++) REDS[nG][wg][i] = ps[i];
    __syncthreads();
    if (t < 16)
        sh_inv[t] = 1.f / (REDS[t >> 2][0][t & 3] + REDS[t >> 2][1][t & 3]);

    // ---- phase 2: aggregation (8 m-groups, 4n x 8d), cp.async double-buffered ----
    const int g    = t >> 5;        // 0..7
    const int l    = t & 31;
    const int nSub = l >> 3;        // 0..3 (4 n each)
    const int dSub = l & 7;         // 0..7 (8 floats each)

    F2 acc2[4][4];
#pragma unroll
    for (int i = 0; i < 4; i++)
#pragma unroll
        for (int j = 0; j < 4; j++) acc2[i][j] = {0.f, 0.f};

    const unsigned vbufBase = smem_u32p(VBUF);
#pragma unroll
    for (int q = 0; q < 4; q++) {
        int f4 = t + 256 * q;
        int row = f4 >> 4, c = f4 & 15;
        CP_ASYNC16(vbufBase + (unsigned)(row * VPITCH + c * 4) * 4u,
                   &g_src[(size_t)(b * NN + row) * HD + h * 64 + c * 4]);
    }
    CP_COMMIT();

    for (int tile = 0; tile < 8; tile++) {
        CP_WAIT0();
        __syncthreads();

        if (tile < 7) {
            const unsigned nb = vbufBase + (unsigned)(((tile + 1) & 1) * VBUF_SZ) * 4u;
#pragma unroll
            for (int q = 0; q < 4; q++) {
                int f4 = t + 256 * q;
                int row = f4 >> 4, c = f4 & 15;
                CP_ASYNC16(nb + (unsigned)(row * VPITCH + c * 4) * 4u,
                           &g_src[(size_t)(b * NN + (tile + 1) * 64 + row) * HD + h * 64 + c * 4]);
            }
            CP_COMMIT();
        }
        const float* VB = &VBUF[(tile & 1) * VBUF_SZ];

#pragma unroll
        for (int mm = 0; mm < 8; mm++) {
            const int mloc = g * 8 + mm;
            const int m = tile * 64 + mloc;
            float4 v01 = *(const float4*)&VB[mloc * VPITCH + dSub * 8];
            float4 v23 = *(const float4*)&VB[mloc * VPITCH + dSub * 8 + 4];
            F2 vv[4] = {{v01.x, v01.y}, {v01.z, v01.w}, {v23.x, v23.y}, {v23.z, v23.w}};
#pragma unroll
            for (int i = 0; i < 4; i++) {
                float p = BUF[(nSub * 4 + i) * PPITCH + m];
                F2 pp = {p, p};
#pragma unroll
                for (int j = 0; j < 4; j++)
                    acc2[i][j] = f2fma(pp, vv[j], acc2[i][j]);
            }
        }
    }

    // ---- two-stage reduction over 8 groups (probs dead -> overlay in BUF) ----
    __syncthreads();
    if (g >= 4) {
#pragma unroll
        for (int i = 0; i < 4; i++)
#pragma unroll
            for (int j = 0; j < 4; j++)
                *(F2*)&BUF[(g - 4) * 1024 + (nSub * 4 + i) * 64 + dSub * 8 + 2 * j]
                    = acc2[i][j];
    }
    __syncthreads();
    if (g < 4) {
#pragma unroll
        for (int i = 0; i < 4; i++)
#pragma unroll
            for (int j = 0; j < 4; j++) {
                F2 o = *(const F2*)&BUF[g * 1024 + (nSub * 4 + i) * 64 + dSub * 8 + 2 * j];
                acc2[i][j] = f2add(acc2[i][j], o);
                *(F2*)&BUF[g * 1024 + (nSub * 4 + i) * 64 + dSub * 8 + 2 * j] = acc2[i][j];
            }
    }
    __syncthreads();

    // ---- final reduce + epilogue (256 threads, 4 outputs each) ----
    {
        const int oIdx = t * 4;
        const int n = oIdx >> 6, d = oIdx & 63;
        float4 s = make_float4(0.f, 0.f, 0.f, 0.f);
#pragma unroll
        for (int g2 = 0; g2 < 4; g2++) {
            float4 r = *(const float4*)&BUF[g2 * 1024 + oIdx];
            s.x += r.x; s.y += r.y; s.z += r.z; s.w += r.w;
        }
        const float inv = sh_inv[n];
        const size_t off = (size_t)(b * NN + bn + n) * HD + h * 64 + d;
        float4 sk = *(const float4*)&g_skip[off];
        float4 bi = *(const float4*)&bias[h * 64 + d];
        float4 o;
        o.x = fmaf(s.x, inv, sk.x + bi.x);
        o.y = fmaf(s.y, inv, sk.y + bi.y);
        o.z = fmaf(s.z, inv, sk.z + bi.z);
        o.w = fmaf(s.w, inv, sk.w + bi.w);
        o.x = (o.x > 0.f) ? o.x : expm1f(o.x);
        o.y = (o.y > 0.f) ? o.y : expm1f(o.y);
        o.z = (o.z > 0.f) ? o.z : expm1f(o.z);
        o.w = (o.w > 0.f) ? o.w : expm1f(o.w);
        *(float4*)&out[off] = o;
    }
}

// ---------------------------------------------------------------------------
// Tail copy (only if extra not divisible by 4)
// ---------------------------------------------------------------------------
__global__ void copy_adj_tail_kernel(
    const int* __restrict__ adj, float* __restrict__ dst, int off, int n)
{
    int i = blockIdx.x * 256 + threadIdx.x;
    if (i < n) dst[off + i] = (float)adj[off + i];
}

extern "C" void kernel_launch(void* const* d_in, const int* in_sizes, int n_in,
                              void* d_out, int out_size)
{
    const float* x       = (const float*)d_in[0];
    const int*   adj     = (const int*)  d_in[1];
    const float* Wsrc    = (const float*)d_in[2];
    const float* Wtgt    = (const float*)d_in[3];
    const float* Wskip   = (const float*)d_in[4];
    const float* scoring = (const float*)d_in[5];
    const float* bias    = (const float*)d_in[6];
    float* out = (float*)d_out;

    const int main_elems = ROWS * HD;               // 524288
    int extra = out_size - main_elems;
    if (extra < 0) extra = 0;
    const int adj_elems = BSZ * NN * NN;            // 524288
    if (extra > adj_elems) extra = adj_elems;
    int n4 = extra >> 2;

    gemm3_kernel<<<dim3(HD / 64, ROWS / 64, 4), 128>>>(
        x, Wsrc, Wtgt, Wskip, scoring,
        (const int4*)adj, (float4*)(out + main_elems), n4);
    attn_kernel<<<dim3(NN / 16, HEADS, BSZ), 256>>>(adj, scoring, bias, out);

    int rem = extra - (n4 << 2);
    if (rem > 0)
        copy_adj_tail_kernel<<<1, 256>>>(adj, out + main_elems, n4 << 2, rem);
}